// round 11
// baseline (speedup 1.0000x reference)
#include <cuda_runtime.h>
#include <math.h>
#include <stdint.h>

#define D_DIM 1024
#define H_DIM 1024
#define E_DIM 64
#define M_TOTAL 65536
#define G1_TILES_TC ((M_TOTAL / 128) * (H_DIM / 128))   // 4096 (BN=128, tcgen05)
#define G1_TILES_FB ((M_TOTAL / 128) * (H_DIM / 256))   // 2048 (fallback)

#if defined(__CUDA_ARCH__) && (__CUDA_ARCH__ >= 1000) && \
    (defined(__CUDA_ARCH_FEAT_SM103_ALL) || defined(__CUDA_ARCH_FEAT_SM100_ALL) || \
     defined(__CUDA_ARCH_SPECIFIC__) || defined(__CUDA_ARCH_FAMILY_SPECIFIC__))
#define HAS_TCGEN05 1
#else
#define HAS_TCGEN05 0
#endif

__device__ float g_H[(size_t)M_TOTAL * H_DIM];   // 256 MB hidden activations

// ---------------- PTX helpers ------------------------------------------------
__device__ __forceinline__ uint32_t smem_u32(const void* p) {
    uint32_t a;
    asm("{ .reg .u64 t; cvta.to.shared.u64 t, %1; cvt.u32.u64 %0, t; }"
        : "=r"(a) : "l"(p));
    return a;
}

#define SWZ128(o) ((o) ^ (((o) >> 3) & 0x70))

__device__ __forceinline__ void mbar_init(uint32_t mbar, uint32_t cnt) {
    asm volatile("mbarrier.init.shared.b64 [%0], %1;" :: "r"(mbar), "r"(cnt) : "memory");
}
__device__ __forceinline__ void mbar_wait(uint32_t mbar, uint32_t parity) {
    asm volatile(
        "{\n\t"
        ".reg .pred P;\n\t"
        "WL%=:\n\t"
        "mbarrier.try_wait.parity.shared::cta.b64 P, [%0], %1, 0x989680;\n\t"
        "@P bra WD%=;\n\t"
        "bra WL%=;\n\t"
        "WD%=:\n\t"
        "}"
        :: "r"(mbar), "r"(parity) : "memory");
}
__device__ __forceinline__ void mbar_arrive(uint32_t mbar) {
    asm volatile("mbarrier.arrive.shared.b64 _, [%0];" :: "r"(mbar) : "memory");
}
__device__ __forceinline__ void fence_proxy_async_cta() {
    asm volatile("fence.proxy.async.shared::cta;" ::: "memory");
}

__device__ __forceinline__ float tf32_rnd(float a) {
    uint32_t r;
    asm("cvt.rna.tf32.f32 %0, %1;" : "=r"(r) : "f"(a));
    return __uint_as_float(r);
}
__device__ __forceinline__ void split4(float4 v, float4& h, float4& l) {
    h.x = tf32_rnd(v.x); l.x = tf32_rnd(v.x - h.x);
    h.y = tf32_rnd(v.y); l.y = tf32_rnd(v.y - h.y);
    h.z = tf32_rnd(v.z); l.z = tf32_rnd(v.z - h.z);
    h.w = tf32_rnd(v.w); l.w = tf32_rnd(v.w - h.w);
}

#if HAS_TCGEN05
__device__ __forceinline__ uint64_t make_desc_sw128(uint32_t addr) {
    const uint64_t base = (2ull << 61) | (1ull << 46) | (64ull << 32) | (1ull << 16);
    return base | ((uint64_t)(addr >> 4) & 0x3FFF);
}
// SS form (A desc in smem)
__device__ __forceinline__ void mma_tf32_ss(uint32_t d_tmem, uint64_t a_desc,
                                            uint64_t b_desc, uint32_t idesc,
                                            uint32_t enable_d) {
    asm volatile(
        "{\n\t"
        ".reg .pred p;\n\t"
        "setp.ne.u32 p, %5, 0;\n\t"
        "tcgen05.mma.cta_group::1.kind::tf32 [%0], %1, %2, %3, {%4, %4, %4, %4}, p;\n\t"
        "}"
        :: "r"(d_tmem), "l"(a_desc), "l"(b_desc), "r"(idesc), "r"(0u), "r"(enable_d)
        : "memory");
}
// TS form (A in TMEM)
__device__ __forceinline__ void mma_tf32_ts(uint32_t d_tmem, uint32_t a_tmem,
                                            uint64_t b_desc, uint32_t idesc,
                                            uint32_t enable_d) {
    asm volatile(
        "{\n\t"
        ".reg .pred p;\n\t"
        "setp.ne.u32 p, %5, 0;\n\t"
        "tcgen05.mma.cta_group::1.kind::tf32 [%0], [%1], %2, %3, {%4, %4, %4, %4}, p;\n\t"
        "}"
        :: "r"(d_tmem), "r"(a_tmem), "l"(b_desc), "r"(idesc), "r"(0u), "r"(enable_d)
        : "memory");
}
__device__ __forceinline__ void tc_commit(uint32_t mbar) {
    asm volatile(
        "tcgen05.commit.cta_group::1.mbarrier::arrive::one.shared::cluster.b64 [%0];"
        :: "r"(mbar) : "memory");
}
__device__ __forceinline__ void tc_alloc(uint32_t slot, uint32_t ncols) {
    asm volatile("tcgen05.alloc.cta_group::1.sync.aligned.shared::cta.b32 [%0], %1;"
                 :: "r"(slot), "r"(ncols) : "memory");
}
__device__ __forceinline__ void tc_dealloc(uint32_t tmem, uint32_t ncols) {
    asm volatile("tcgen05.relinquish_alloc_permit.cta_group::1.sync.aligned;");
    asm volatile("tcgen05.dealloc.cta_group::1.sync.aligned.b32 %0, %1;" :: "r"(tmem), "r"(ncols));
}
__device__ __forceinline__ void tc_fence_after() {
    asm volatile("tcgen05.fence::after_thread_sync;" ::: "memory");
}
__device__ __forceinline__ void tc_fence_before() {
    asm volatile("tcgen05.fence::before_thread_sync;" ::: "memory");
}
__device__ __forceinline__ void tc_wait_ld() {
    asm volatile("tcgen05.wait::ld.sync.aligned;" ::: "memory");
}
__device__ __forceinline__ void tc_wait_st() {
    asm volatile("tcgen05.wait::st.sync.aligned;" ::: "memory");
}

#define TC_LD_X32(r, a)                                                       \
    asm volatile(                                                             \
        "tcgen05.ld.sync.aligned.32x32b.x32.b32 "                             \
        "{%0, %1, %2, %3, %4, %5, %6, %7, "                                   \
        " %8, %9, %10, %11, %12, %13, %14, %15, "                             \
        " %16, %17, %18, %19, %20, %21, %22, %23, "                           \
        " %24, %25, %26, %27, %28, %29, %30, %31}, [%32];"                    \
        : "=r"((r)[0]),  "=r"((r)[1]),  "=r"((r)[2]),  "=r"((r)[3]),          \
          "=r"((r)[4]),  "=r"((r)[5]),  "=r"((r)[6]),  "=r"((r)[7]),          \
          "=r"((r)[8]),  "=r"((r)[9]),  "=r"((r)[10]), "=r"((r)[11]),         \
          "=r"((r)[12]), "=r"((r)[13]), "=r"((r)[14]), "=r"((r)[15]),         \
          "=r"((r)[16]), "=r"((r)[17]), "=r"((r)[18]), "=r"((r)[19]),         \
          "=r"((r)[20]), "=r"((r)[21]), "=r"((r)[22]), "=r"((r)[23]),         \
          "=r"((r)[24]), "=r"((r)[25]), "=r"((r)[26]), "=r"((r)[27]),         \
          "=r"((r)[28]), "=r"((r)[29]), "=r"((r)[30]), "=r"((r)[31])          \
        : "r"(a))

#define TC_ST_X64(a, r)                                                       \
    asm volatile(                                                             \
        "tcgen05.st.sync.aligned.32x32b.x64.b32 [%0], "                       \
        "{%1, %2, %3, %4, %5, %6, %7, %8, "                                   \
        " %9, %10, %11, %12, %13, %14, %15, %16, "                            \
        " %17, %18, %19, %20, %21, %22, %23, %24, "                           \
        " %25, %26, %27, %28, %29, %30, %31, %32, "                           \
        " %33, %34, %35, %36, %37, %38, %39, %40, "                           \
        " %41, %42, %43, %44, %45, %46, %47, %48, "                           \
        " %49, %50, %51, %52, %53, %54, %55, %56, "                           \
        " %57, %58, %59, %60, %61, %62, %63, %64};"                           \
        :: "r"(a),                                                            \
           "r"((r)[0]),  "r"((r)[1]),  "r"((r)[2]),  "r"((r)[3]),             \
           "r"((r)[4]),  "r"((r)[5]),  "r"((r)[6]),  "r"((r)[7]),             \
           "r"((r)[8]),  "r"((r)[9]),  "r"((r)[10]), "r"((r)[11]),            \
           "r"((r)[12]), "r"((r)[13]), "r"((r)[14]), "r"((r)[15]),            \
           "r"((r)[16]), "r"((r)[17]), "r"((r)[18]), "r"((r)[19]),            \
           "r"((r)[20]), "r"((r)[21]), "r"((r)[22]), "r"((r)[23]),            \
           "r"((r)[24]), "r"((r)[25]), "r"((r)[26]), "r"((r)[27]),            \
           "r"((r)[28]), "r"((r)[29]), "r"((r)[30]), "r"((r)[31]),            \
           "r"((r)[32]), "r"((r)[33]), "r"((r)[34]), "r"((r)[35]),            \
           "r"((r)[36]), "r"((r)[37]), "r"((r)[38]), "r"((r)[39]),            \
           "r"((r)[40]), "r"((r)[41]), "r"((r)[42]), "r"((r)[43]),            \
           "r"((r)[44]), "r"((r)[45]), "r"((r)[46]), "r"((r)[47]),            \
           "r"((r)[48]), "r"((r)[49]), "r"((r)[50]), "r"((r)[51]),            \
           "r"((r)[52]), "r"((r)[53]), "r"((r)[54]), "r"((r)[55]),            \
           "r"((r)[56]), "r"((r)[57]), "r"((r)[58]), "r"((r)[59]),            \
           "r"((r)[60]), "r"((r)[61]), "r"((r)[62]), "r"((r)[63])             \
        : "memory")
#endif  // HAS_TCGEN05

__device__ __forceinline__ float gelu_erf(float v) {
    return 0.5f * v * (1.0f + erff(v * 0.7071067811865476f));
}

// ============================================================================
// GEMM1 (persistent, TS mode): H = gelu(x @ W1^T + b1). 3xTF32.
// BM=128, BN=128, BK=32, 2-stage. A(hi/lo) lives in TMEM (no smem for A).
// 416 thr: warps0-3 A->TMEM | warps4-7 B->smem | warp8 MMA | warps9-12 epi.
// TMEM cols: D0 0..127, D1 128..255, A stage s at 256+s*64 (hi 32 + lo 32).
// ============================================================================
#define BK 32
#define NIT (D_DIM / BK)
#define STG_B_BYTES 32768           // Bhi 16K + Blo 16K
#define OFF_BLO 16384
#define GEMM1_SMEM (1024 + 2 * STG_B_BYTES)
#define TM_A_OFF 256

// mbar offsets: full[s]=64+16s (cnt 8), empty[s]=+8 (cnt 1, commit)
//               tdone[b]=96+16b (cnt 1, commit), dfree[b]=+8 (cnt 4)
#define MB_FULL(s)  (64 + 16 * (s))
#define MB_EMPTY(s) (64 + 16 * (s) + 8)
#define MB_TDONE(b) (96 + 16 * (b))
#define MB_DFREE(b) (96 + 16 * (b) + 8)

// idesc: dtype f32, a/b tf32, N=128, M=128
#define IDESC_TS ((1u << 4) | (2u << 7) | (2u << 10) | ((128u / 8) << 17) | ((128u / 16) << 24))

extern "C" __global__ void __launch_bounds__(416, 1) gemm1_kernel(
    const float* __restrict__ x, const float* __restrict__ W1,
    const float* __restrict__ b1, float* __restrict__ Hout)
{
    extern __shared__ __align__(1024) char smem[];
    const int tid = threadIdx.x;

#if HAS_TCGEN05
    const uint32_t sbase = smem_u32(smem);
    const int lane = tid & 31;

    if (tid == 0) {
#pragma unroll
        for (int s = 0; s < 2; s++) {
            mbar_init(sbase + MB_FULL(s), 8);
            mbar_init(sbase + MB_EMPTY(s), 1);
            mbar_init(sbase + MB_TDONE(s), 1);
            mbar_init(sbase + MB_DFREE(s), 4);
        }
    }
    if (tid >= 256 && tid < 288) tc_alloc(sbase, 512);
    __syncthreads();

    uint32_t tmem_base;
    asm volatile("ld.shared.b32 %0, [%1];" : "=r"(tmem_base) : "r"(sbase));

    if (tid < 128) {
        // ------------- A producers: x row -> split -> TMEM (STTM x64) --------
        const int row = tid;                       // 0..127
        const uint32_t warp_off = (uint32_t)(tid >> 5) << 21;
        uint32_t pe[2] = {1, 1};

        for (int t = blockIdx.x; t < G1_TILES_TC; t += gridDim.x) {
            const int bm = (t >> 3) * 128;
            const float* pA = x + (size_t)(bm + row) * D_DIM;

            for (int i = 0; i < NIT; i++) {
                const int s = i & 1;
                mbar_wait(sbase + MB_EMPTY(s), pe[s]); pe[s] ^= 1;

                const int k0 = i * BK;
                uint32_t v[64];   // hi[0:32], lo[32:64]
#pragma unroll
                for (int q = 0; q < 8; q++) {
                    float4 f = *(const float4*)(pA + k0 + q * 4);
                    float4 h, l; split4(f, h, l);
                    v[q * 4 + 0] = __float_as_uint(h.x);
                    v[q * 4 + 1] = __float_as_uint(h.y);
                    v[q * 4 + 2] = __float_as_uint(h.z);
                    v[q * 4 + 3] = __float_as_uint(h.w);
                    v[32 + q * 4 + 0] = __float_as_uint(l.x);
                    v[32 + q * 4 + 1] = __float_as_uint(l.y);
                    v[32 + q * 4 + 2] = __float_as_uint(l.z);
                    v[32 + q * 4 + 3] = __float_as_uint(l.w);
                }
                TC_ST_X64(tmem_base + TM_A_OFF + s * 64 + warp_off, v);
                tc_wait_st();
                tc_fence_before();
                __syncwarp();
                if (lane == 0) mbar_arrive(sbase + MB_FULL(s));
            }
        }
    } else if (tid < 256) {
        // ------------- B producers: W1 row -> split -> smem ------------------
        const int row = tid - 128;                 // 0..127
        uint32_t off[8];
#pragma unroll
        for (int q = 0; q < 8; q++)
            off[q] = SWZ128((uint32_t)row * 128 + q * 16);

        uint32_t pe[2] = {1, 1};

        for (int t = blockIdx.x; t < G1_TILES_TC; t += gridDim.x) {
            const int bn = (t & 7) * 128;
            const float* pB = W1 + (size_t)(bn + row) * D_DIM;

            for (int i = 0; i < NIT; i++) {
                const int s = i & 1;
                mbar_wait(sbase + MB_EMPTY(s), pe[s]); pe[s] ^= 1;

                const int k0 = i * BK;
                char* st = smem + 1024 + s * STG_B_BYTES;
#pragma unroll
                for (int q = 0; q < 8; q++) {
                    float4 f = *(const float4*)(pB + k0 + q * 4);
                    float4 h, l; split4(f, h, l);
                    *(float4*)(st + off[q])           = h;
                    *(float4*)(st + OFF_BLO + off[q]) = l;
                }
                fence_proxy_async_cta();
                __syncwarp();
                if (lane == 0) mbar_arrive(sbase + MB_FULL(s));
            }
        }
    } else if (tid == 256) {
        // ------------- MMA issuer (TS mode) ----------------------------------
        uint32_t pf[2] = {0, 0}, pd[2] = {0, 0};
        int lt = 0;
        for (int t = blockIdx.x; t < G1_TILES_TC; t += gridDim.x) {
            const int b = lt & 1;
            if (lt >= 2) { mbar_wait(sbase + MB_DFREE(b), pd[b]); pd[b] ^= 1; }
            const uint32_t dD = tmem_base + b * 128;

            for (int i = 0; i < NIT; i++) {
                const int s = i & 1;
                mbar_wait(sbase + MB_FULL(s), pf[s]); pf[s] ^= 1;
                tc_fence_after();

                const uint32_t aBase = tmem_base + TM_A_OFF + s * 64;
                uint64_t dBh = make_desc_sw128(sbase + 1024 + s * STG_B_BYTES);
                uint64_t dBl = dBh + (OFF_BLO >> 4);
#pragma unroll
                for (int ks = 0; ks < 4; ks++) {
                    mma_tf32_ts(dD, aBase + ks * 8,      dBh + 2 * ks, IDESC_TS,
                                (i == 0 && ks == 0) ? 0u : 1u);
                    mma_tf32_ts(dD, aBase + ks * 8,      dBl + 2 * ks, IDESC_TS, 1u);
                    mma_tf32_ts(dD, aBase + 32 + ks * 8, dBh + 2 * ks, IDESC_TS, 1u);
                }
                tc_commit(sbase + MB_EMPTY(s));
            }
            tc_commit(sbase + MB_TDONE(b));
            lt++;
        }
    } else if (tid >= 288) {
        // ------------- epilogue: 4 warps, 128 rows x 128 cols ----------------
        const int sub = (tid >> 5) & 3;
        uint32_t pt[2] = {0, 0};
        int lt = 0;
        for (int t = blockIdx.x; t < G1_TILES_TC; t += gridDim.x) {
            const int b = lt & 1;
            mbar_wait(sbase + MB_TDONE(b), pt[b]); pt[b] ^= 1;
            tc_fence_after();

            const int bm = (t >> 3) * 128;
            const int bn = (t & 7) * 128;
            const int row = bm + sub * 32 + lane;
            float* hrow = Hout + (size_t)row * H_DIM + bn;
            const float* brow = b1 + bn;
            const uint32_t dD = tmem_base + b * 128;
#pragma unroll
            for (int ch = 0; ch < 4; ch++) {
                uint32_t r[32];
                TC_LD_X32(r, dD + ch * 32);
                tc_wait_ld();
#pragma unroll
                for (int q = 0; q < 8; q++) {
                    float4 bias = *(const float4*)(brow + ch * 32 + q * 4);
                    float4 o;
                    o.x = gelu_erf(__uint_as_float(r[q * 4 + 0]) + bias.x);
                    o.y = gelu_erf(__uint_as_float(r[q * 4 + 1]) + bias.y);
                    o.z = gelu_erf(__uint_as_float(r[q * 4 + 2]) + bias.z);
                    o.w = gelu_erf(__uint_as_float(r[q * 4 + 3]) + bias.w);
                    *(float4*)(hrow + ch * 32 + q * 4) = o;
                }
            }
            tc_fence_before();
            __syncwarp();
            if (lane == 0) mbar_arrive(sbase + MB_DFREE(b));
            lt++;
        }
    }

    __syncthreads();
    if (tid >= 256 && tid < 288) tc_dealloc(tmem_base, 512);

#else  // ---------- FFMA fallback (generic pass; persistent) -----------------
    float* As = (float*)smem;
    float* Bs = As + 8 * 128;

    const int tx = tid & 15;
    const int ty = tid >> 4;
    const int lr = tid >> 1;
    const int lc = (tid & 1) * 4;

    for (int t = blockIdx.x; t < G1_TILES_FB; t += gridDim.x) {
        const int bm = (t >> 2) * 128;
        for (int half = 0; half < 2; half++) {
            const int bn = (t & 3) * 256 + half * 128;
            float acc[8][8];
#pragma unroll
            for (int i = 0; i < 8; i++)
#pragma unroll
                for (int j = 0; j < 8; j++) acc[i][j] = 0.0f;

            for (int k0 = 0; k0 < D_DIM; k0 += 8) {
                __syncthreads();
                if (tid < 256) {
                    float4 a4 = *(const float4*)(x  + (size_t)(bm + lr) * D_DIM + lc + k0);
                    float4 b4 = *(const float4*)(W1 + (size_t)(bn + lr) * D_DIM + lc + k0);
                    As[(lc + 0) * 128 + lr] = a4.x; As[(lc + 1) * 128 + lr] = a4.y;
                    As[(lc + 2) * 128 + lr] = a4.z; As[(lc + 3) * 128 + lr] = a4.w;
                    Bs[(lc + 0) * 128 + lr] = b4.x; Bs[(lc + 1) * 128 + lr] = b4.y;
                    Bs[(lc + 2) * 128 + lr] = b4.z; Bs[(lc + 3) * 128 + lr] = b4.w;
                }
                __syncthreads();
                if (tid < 256) {
#pragma unroll
                    for (int kk = 0; kk < 8; kk++) {
                        float a[8], b[8];
                        *(float4*)(a)     = *(const float4*)&As[kk * 128 + ty * 8];
                        *(float4*)(a + 4) = *(const float4*)&As[kk * 128 + ty * 8 + 4];
                        *(float4*)(b)     = *(const float4*)&Bs[kk * 128 + tx * 8];
                        *(float4*)(b + 4) = *(const float4*)&Bs[kk * 128 + tx * 8 + 4];
#pragma unroll
                        for (int i = 0; i < 8; i++)
#pragma unroll
                            for (int j = 0; j < 8; j++)
                                acc[i][j] = fmaf(a[i], b[j], acc[i][j]);
                    }
                }
            }

            if (tid < 256) {
                float bias[8];
                *(float4*)(bias)     = *(const float4*)&b1[bn + tx * 8];
                *(float4*)(bias + 4) = *(const float4*)&b1[bn + tx * 8 + 4];
#pragma unroll
                for (int i = 0; i < 8; i++) {
                    const int row = bm + ty * 8 + i;
                    float o[8];
#pragma unroll
                    for (int j = 0; j < 8; j++)
                        o[j] = gelu_erf(acc[i][j] + bias[j]);
                    float* dst = Hout + (size_t)row * H_DIM + bn + tx * 8;
                    *(float4*)(dst)     = make_float4(o[0], o[1], o[2], o[3]);
                    *(float4*)(dst + 4) = make_float4(o[4], o[5], o[6], o[7]);
                }
            }
            __syncthreads();
        }
    }
#endif
}

// ============================================================================
// GEMM2: logits = (H @ W2^T + b2)/temp; top-2 softmax.  3xTF32, 4-stage pipe,
// in-register split. 288 threads. (unchanged, proven 123 us)
// ============================================================================
#define NIT2 (H_DIM / 32)
#define STAGE2_BYTES 49152
#define OFF2_HLO 16384
#define OFF2_WHI 32768
#define OFF2_WLO 40960
#define GEMM2_SMEM (1024 + 4 * STAGE2_BYTES)

#define IDESC_G2 ((1u << 4) | (2u << 7) | (2u << 10) | ((64u / 8) << 17) | ((128u / 16) << 24))

extern "C" __global__ void __launch_bounds__(288, 1) gemm2_kernel(
    const float* __restrict__ Hin, const float* __restrict__ W2,
    const float* __restrict__ b2, const float* __restrict__ log_temp,
    float* __restrict__ out)
{
    extern __shared__ __align__(1024) char smem[];
    const int tid = threadIdx.x;
    const int bm = blockIdx.x * 128;

#if HAS_TCGEN05
    const uint32_t sbase = smem_u32(smem);

    if (tid == 0) {
#pragma unroll
        for (int s = 0; s < 4; s++) {
            mbar_init(sbase + 64 + 16 * s, 256);
            mbar_init(sbase + 64 + 16 * s + 8, 1);
        }
    }
    if (tid >= 256) tc_alloc(sbase, 64);
    __syncthreads();

    uint32_t tmem_base;
    asm volatile("ld.shared.b32 %0, [%1];" : "=r"(tmem_base) : "r"(sbase));

    if (tid < 256) {
        const int r0 = tid >> 3;
        const int c4 = tid & 7;
        uint32_t offH[4], offW[2];
#pragma unroll
        for (int j = 0; j < 4; j++)
            offH[j] = SWZ128((uint32_t)(r0 + 32 * j) * 128 + c4 * 16);
#pragma unroll
        for (int j = 0; j < 2; j++)
            offW[j] = SWZ128((uint32_t)(r0 + 32 * j) * 128 + c4 * 16);

        const float* pH = Hin + (size_t)(bm + r0) * H_DIM + c4 * 4;
        const float* pW = W2  + (size_t)r0 * H_DIM + c4 * 4;

        uint32_t pe[4] = {1, 1, 1, 1};

        for (int ii = 0; ii < NIT2 / 4; ii++) {
#pragma unroll
            for (int s = 0; s < 4; s++) {
                const int i = ii * 4 + s;
                const uint32_t mb_full  = sbase + 64 + 16 * s;
                const uint32_t mb_empty = mb_full + 8;
                mbar_wait(mb_empty, pe[s]); pe[s] ^= 1;

                const int k0 = i * 32;
                char* st = smem + 1024 + s * STAGE2_BYTES;
#pragma unroll
                for (int j = 0; j < 4; j++) {
                    float4 v = *(const float4*)(pH + (size_t)(32 * j) * H_DIM + k0);
                    float4 h, l; split4(v, h, l);
                    *(float4*)(st + offH[j])            = h;
                    *(float4*)(st + OFF2_HLO + offH[j]) = l;
                }
#pragma unroll
                for (int j = 0; j < 2; j++) {
                    float4 v = *(const float4*)(pW + (size_t)(32 * j) * H_DIM + k0);
                    float4 h, l; split4(v, h, l);
                    *(float4*)(st + OFF2_WHI + offW[j]) = h;
                    *(float4*)(st + OFF2_WLO + offW[j]) = l;
                }
                fence_proxy_async_cta();
                mbar_arrive(mb_full);
            }
        }

#pragma unroll
        for (int s = 0; s < 4; s++)
            mbar_wait(sbase + 64 + 16 * s + 8, pe[s]);
        tc_fence_after();
    } else if (tid == 256) {
        uint32_t pf[4] = {0, 0, 0, 0};
        for (int ii = 0; ii < NIT2 / 4; ii++) {
#pragma unroll
            for (int s = 0; s < 4; s++) {
                const int i = ii * 4 + s;
                const uint32_t mb_full  = sbase + 64 + 16 * s;
                const uint32_t mb_empty = mb_full + 8;
                mbar_wait(mb_full, pf[s]); pf[s] ^= 1;

                uint32_t sb = sbase + 1024 + s * STAGE2_BYTES;
                uint64_t dHh = make_desc_sw128(sb);
                uint64_t dHl = make_desc_sw128(sb + OFF2_HLO);
                uint64_t dWh = make_desc_sw128(sb + OFF2_WHI);
                uint64_t dWl = make_desc_sw128(sb + OFF2_WLO);
#pragma unroll
                for (int ks = 0; ks < 4; ks++) {
                    mma_tf32_ss(tmem_base, dHh + 2 * ks, dWh + 2 * ks, IDESC_G2,
                                (i == 0 && ks == 0) ? 0u : 1u);
                    mma_tf32_ss(tmem_base, dHh + 2 * ks, dWl + 2 * ks, IDESC_G2, 1u);
                    mma_tf32_ss(tmem_base, dHl + 2 * ks, dWh + 2 * ks, IDESC_G2, 1u);
                }
                tc_commit(mb_empty);
            }
        }
    }
    __syncthreads();

    float* Ls  = (float*)(smem + 1024);            // [128][65]
    float* p1s = (float*)(smem + 1024 + 33280);
    float* p2s = p1s + 128;
    int*   i1s = (int*)(p2s + 128);
    int*   i2s = i1s + 128;

    float t = expf(*log_temp);
    t = fminf(fmaxf(t, 1e-3f), 100.0f);
    const float it = 1.0f / t;

    if (tid < 256) {
        const int w = tid >> 5, lane = tid & 31;
        const int row = (w & 3) * 32 + lane;
        const int colbase = (w >> 2) * 32;
        uint32_t r[32];
        TC_LD_X32(r, tmem_base + colbase);
        tc_wait_ld();
#pragma unroll
        for (int c = 0; c < 32; c++)
            Ls[row * 65 + colbase + c] =
                (__uint_as_float(r[c]) + b2[colbase + c]) * it;
    }
    __syncthreads();

    if (tid < 128) {
        float m1 = -INFINITY, m2 = -INFINITY;
        int i1 = -1, i2 = -1;
#pragma unroll 8
        for (int e = 0; e < E_DIM; e++) {
            float v = Ls[tid * 65 + e];
            if (v > m1) { m2 = m1; i2 = i1; m1 = v; i1 = e; }
            else if (v > m2) { m2 = v; i2 = e; }
        }
        float ed = expf(m2 - m1);
        float s = 1.0f / (1.0f + ed);
        p1s[tid] = s;
        p2s[tid] = ed * s;
        i1s[tid] = i1;
        i2s[tid] = i2;
    }
    __syncthreads();

    if (tid < 256) {
        for (int idx = tid; idx < 128 * E_DIM; idx += 256) {
            const int r = idx >> 6;
            const int e = idx & 63;
            float v = 0.0f;
            if (e == i1s[r]) v = p1s[r];
            else if (e == i2s[r]) v = p2s[r];
            out[(size_t)(bm + r) * E_DIM + e] = v;
        }
    }

    __syncthreads();
    if (tid >= 256) tc_dealloc(tmem_base, 64);

#else  // ---------- FFMA fallback (generic pass) -----------------------------
    float* Hs  = (float*)smem;
    float* Ws  = Hs + 16 * 128;
    float* Ls  = Ws + 16 * 64;
    float* p1s = Ls + 128 * 65;
    float* p2s = p1s + 128;
    int*   i1s = (int*)(p2s + 128);
    int*   i2s = i1s + 128;

    const int tx = tid & 15;
    const int ty = tid >> 4;
    const int hr0 = tid >> 2;
    const int hc0 = (tid & 3) * 4;
    const int hr1 = (tid + 256) >> 2;
    const int wr = tid >> 2;
    const int wc = (tid & 3) * 4;

    float acc[8][4];
#pragma unroll
    for (int i = 0; i < 8; i++)
#pragma unroll
        for (int j = 0; j < 4; j++) acc[i][j] = 0.0f;

    for (int k0 = 0; k0 < H_DIM; k0 += 16) {
        __syncthreads();
        if (tid < 256) {
            float4 h0 = *(const float4*)(Hin + (size_t)(bm + hr0) * H_DIM + k0 + hc0);
            float4 h1 = *(const float4*)(Hin + (size_t)(bm + hr1) * H_DIM + k0 + hc0);
            float4 w4 = *(const float4*)(W2  + (size_t)wr * H_DIM + k0 + wc);
            Hs[(hc0 + 0) * 128 + hr0] = h0.x; Hs[(hc0 + 1) * 128 + hr0] = h0.y;
            Hs[(hc0 + 2) * 128 + hr0] = h0.z; Hs[(hc0 + 3) * 128 + hr0] = h0.w;
            Hs[(hc0 + 0) * 128 + hr1] = h1.x; Hs[(hc0 + 1) * 128 + hr1] = h1.y;
            Hs[(hc0 + 2) * 128 + hr1] = h1.z; Hs[(hc0 + 3) * 128 + hr1] = h1.w;
            Ws[(wc + 0) * 64 + wr] = w4.x; Ws[(wc + 1) * 64 + wr] = w4.y;
            Ws[(wc + 2) * 64 + wr] = w4.z; Ws[(wc + 3) * 64 + wr] = w4.w;
        }
        __syncthreads();
        if (tid < 256) {
#pragma unroll
            for (int kk = 0; kk < 16; kk++) {
                float a[8], b[4];
                *(float4*)(a)     = *(const float4*)&Hs[kk * 128 + ty * 8];
                *(float4*)(a + 4) = *(const float4*)&Hs[kk * 128 + ty * 8 + 4];
                *(float4*)(b)     = *(const float4*)&Ws[kk * 64 + tx * 4];
#pragma unroll
                for (int i = 0; i < 8; i++)
#pragma unroll
                    for (int j = 0; j < 4; j++)
                        acc[i][j] = fmaf(a[i], b[j], acc[i][j]);
            }
        }
    }

    float t = expf(*log_temp);
    t = fminf(fmaxf(t, 1e-3f), 100.0f);
    const float it = 1.0f / t;

    if (tid < 256) {
#pragma unroll
        for (int i = 0; i < 8; i++)
#pragma unroll
            for (int j = 0; j < 4; j++) {
                const int col = tx * 4 + j;
                Ls[(ty * 8 + i) * 65 + col] = (acc[i][j] + b2[col]) * it;
            }
    }
    __syncthreads();

    if (tid < 128) {
        float m1 = -INFINITY, m2 = -INFINITY;
        int i1 = -1, i2 = -1;
#pragma unroll 8
        for (int e = 0; e < E_DIM; e++) {
            float v = Ls[tid * 65 + e];
            if (v > m1) { m2 = m1; i2 = i1; m1 = v; i1 = e; }
            else if (v > m2) { m2 = v; i2 = e; }
        }
        float ed = expf(m2 - m1);
        float s = 1.0f / (1.0f + ed);
        p1s[tid] = s;
        p2s[tid] = ed * s;
        i1s[tid] = i1;
        i2s[tid] = i2;
    }
    __syncthreads();

    if (tid < 256) {
        for (int idx = tid; idx < 128 * E_DIM; idx += 256) {
            const int r = idx >> 6;
            const int e = idx & 63;
            float v = 0.0f;
            if (e == i1s[r]) v = p1s[r];
            else if (e == i2s[r]) v = p2s[r];
            out[(size_t)(bm + r) * E_DIM + e] = v;
        }
    }
#endif
}

// ---------------- launcher ---------------------------------------------------
extern "C" void kernel_launch(void* const* d_in, const int* in_sizes, int n_in,
                              void* d_out, int out_size) {
    const float* x  = (const float*)d_in[0];
    const float* W1 = (const float*)d_in[1];
    const float* b1 = (const float*)d_in[2];
    const float* W2 = (const float*)d_in[3];
    const float* b2 = (const float*)d_in[4];
    const float* lt = (const float*)d_in[5];
    float* out = (float*)d_out;

    const int M = in_sizes[0] / D_DIM;   // 65536

    float* Hbuf;
    cudaGetSymbolAddress((void**)&Hbuf, g_H);

    static int nsm = 0;
    if (!nsm) {
        cudaDeviceGetAttribute(&nsm, cudaDevAttrMultiProcessorCount, 0);
        cudaFuncSetAttribute(gemm1_kernel,
                             cudaFuncAttributeMaxDynamicSharedMemorySize, GEMM1_SMEM);
        cudaFuncSetAttribute(gemm2_kernel,
                             cudaFuncAttributeMaxDynamicSharedMemorySize, GEMM2_SMEM);
    }

    gemm1_kernel<<<nsm, 416, GEMM1_SMEM>>>(x, W1, b1, Hbuf);

    dim3 grid2(M / 128);
    gemm2_kernel<<<grid2, 288, GEMM2_SMEM>>>(Hbuf, W2, b2, lt, out);
}

// round 13
// speedup vs baseline: 1.6297x; 1.6297x over previous
#include <cuda_runtime.h>
#include <math.h>
#include <stdint.h>

#define D_DIM 1024
#define H_DIM 1024
#define E_DIM 64
#define M_TOTAL 65536
#define G1_TILES ((M_TOTAL / 128) * (H_DIM / 256))   // 2048

#if defined(__CUDA_ARCH__) && (__CUDA_ARCH__ >= 1000) && \
    (defined(__CUDA_ARCH_FEAT_SM103_ALL) || defined(__CUDA_ARCH_FEAT_SM100_ALL) || \
     defined(__CUDA_ARCH_SPECIFIC__) || defined(__CUDA_ARCH_FAMILY_SPECIFIC__))
#define HAS_TCGEN05 1
#else
#define HAS_TCGEN05 0
#endif

__device__ float g_H[(size_t)M_TOTAL * H_DIM];   // 256 MB hidden activations

// ---------------- PTX helpers ------------------------------------------------
__device__ __forceinline__ uint32_t smem_u32(const void* p) {
    uint32_t a;
    asm("{ .reg .u64 t; cvta.to.shared.u64 t, %1; cvt.u32.u64 %0, t; }"
        : "=r"(a) : "l"(p));
    return a;
}

#define SWZ128(o) ((o) ^ (((o) >> 3) & 0x70))

__device__ __forceinline__ void mbar_init(uint32_t mbar, uint32_t cnt) {
    asm volatile("mbarrier.init.shared.b64 [%0], %1;" :: "r"(mbar), "r"(cnt) : "memory");
}
__device__ __forceinline__ void mbar_wait(uint32_t mbar, uint32_t parity) {
    asm volatile(
        "{\n\t"
        ".reg .pred P;\n\t"
        "WL%=:\n\t"
        "mbarrier.try_wait.parity.shared::cta.b64 P, [%0], %1, 0x989680;\n\t"
        "@P bra WD%=;\n\t"
        "bra WL%=;\n\t"
        "WD%=:\n\t"
        "}"
        :: "r"(mbar), "r"(parity) : "memory");
}
__device__ __forceinline__ void mbar_arrive(uint32_t mbar) {
    asm volatile("mbarrier.arrive.shared.b64 _, [%0];" :: "r"(mbar) : "memory");
}
__device__ __forceinline__ void fence_proxy_async_cta() {
    asm volatile("fence.proxy.async.shared::cta;" ::: "memory");
}

__device__ __forceinline__ float tf32_rnd(float a) {
    uint32_t r;
    asm("cvt.rna.tf32.f32 %0, %1;" : "=r"(r) : "f"(a));
    return __uint_as_float(r);
}
__device__ __forceinline__ void split4(float4 v, float4& h, float4& l) {
    h.x = tf32_rnd(v.x); l.x = tf32_rnd(v.x - h.x);
    h.y = tf32_rnd(v.y); l.y = tf32_rnd(v.y - h.y);
    h.z = tf32_rnd(v.z); l.z = tf32_rnd(v.z - h.z);
    h.w = tf32_rnd(v.w); l.w = tf32_rnd(v.w - h.w);
}

#if HAS_TCGEN05
__device__ __forceinline__ uint64_t make_desc_sw128(uint32_t addr) {
    const uint64_t base = (2ull << 61) | (1ull << 46) | (64ull << 32) | (1ull << 16);
    return base | ((uint64_t)(addr >> 4) & 0x3FFF);
}
__device__ __forceinline__ void mma_tf32_ss(uint32_t d_tmem, uint64_t a_desc,
                                            uint64_t b_desc, uint32_t idesc,
                                            uint32_t enable_d) {
    asm volatile(
        "{\n\t"
        ".reg .pred p;\n\t"
        "setp.ne.u32 p, %5, 0;\n\t"
        "tcgen05.mma.cta_group::1.kind::tf32 [%0], %1, %2, %3, {%4, %4, %4, %4}, p;\n\t"
        "}"
        :: "r"(d_tmem), "l"(a_desc), "l"(b_desc), "r"(idesc), "r"(0u), "r"(enable_d)
        : "memory");
}
__device__ __forceinline__ void tc_commit(uint32_t mbar) {
    asm volatile(
        "tcgen05.commit.cta_group::1.mbarrier::arrive::one.shared::cluster.b64 [%0];"
        :: "r"(mbar) : "memory");
}
__device__ __forceinline__ void tc_alloc(uint32_t slot, uint32_t ncols) {
    asm volatile("tcgen05.alloc.cta_group::1.sync.aligned.shared::cta.b32 [%0], %1;"
                 :: "r"(slot), "r"(ncols) : "memory");
}
__device__ __forceinline__ void tc_dealloc(uint32_t tmem, uint32_t ncols) {
    asm volatile("tcgen05.relinquish_alloc_permit.cta_group::1.sync.aligned;");
    asm volatile("tcgen05.dealloc.cta_group::1.sync.aligned.b32 %0, %1;" :: "r"(tmem), "r"(ncols));
}
__device__ __forceinline__ void tc_fence_after() {
    asm volatile("tcgen05.fence::after_thread_sync;" ::: "memory");
}
__device__ __forceinline__ void tc_fence_before() {
    asm volatile("tcgen05.fence::before_thread_sync;" ::: "memory");
}
__device__ __forceinline__ void tc_wait_ld() {
    asm volatile("tcgen05.wait::ld.sync.aligned;" ::: "memory");
}

#define TC_LD_X32(r, a)                                                       \
    asm volatile(                                                             \
        "tcgen05.ld.sync.aligned.32x32b.x32.b32 "                             \
        "{%0, %1, %2, %3, %4, %5, %6, %7, "                                   \
        " %8, %9, %10, %11, %12, %13, %14, %15, "                             \
        " %16, %17, %18, %19, %20, %21, %22, %23, "                           \
        " %24, %25, %26, %27, %28, %29, %30, %31}, [%32];"                    \
        : "=r"((r)[0]),  "=r"((r)[1]),  "=r"((r)[2]),  "=r"((r)[3]),          \
          "=r"((r)[4]),  "=r"((r)[5]),  "=r"((r)[6]),  "=r"((r)[7]),          \
          "=r"((r)[8]),  "=r"((r)[9]),  "=r"((r)[10]), "=r"((r)[11]),         \
          "=r"((r)[12]), "=r"((r)[13]), "=r"((r)[14]), "=r"((r)[15]),         \
          "=r"((r)[16]), "=r"((r)[17]), "=r"((r)[18]), "=r"((r)[19]),         \
          "=r"((r)[20]), "=r"((r)[21]), "=r"((r)[22]), "=r"((r)[23]),         \
          "=r"((r)[24]), "=r"((r)[25]), "=r"((r)[26]), "=r"((r)[27]),         \
          "=r"((r)[28]), "=r"((r)[29]), "=r"((r)[30]), "=r"((r)[31])          \
        : "r"(a))
#endif  // HAS_TCGEN05

__device__ __forceinline__ float gelu_erf(float v) {
    return 0.5f * v * (1.0f + erff(v * 0.7071067811865476f));
}

// ============================================================================
// GEMM1 (persistent): H = gelu(x @ W1^T + b1). 3xTF32, in-register split,
// SOFTWARE-PREFETCHED producers. BM=128, BN=256, BK=32, 2-stage ring.
// 416 thr: 256 prod | warp8 MMA | 4 epi warps. TMEM: two 256-col D buffers.
// ============================================================================
#define BK 32
#define NIT (D_DIM / BK)
#define STAGE_BYTES 98304
#define OFF_ALO 16384
#define OFF_BHI 32768
#define OFF_BLO 65536
#define GEMM1_SMEM (1024 + 2 * STAGE_BYTES)

#define IDESC_G1 ((1u << 4) | (2u << 7) | (2u << 10) | ((256u / 8) << 17) | ((128u / 16) << 24))

extern "C" __global__ void __launch_bounds__(416, 1) gemm1_kernel(
    const float* __restrict__ x, const float* __restrict__ W1,
    const float* __restrict__ b1, float* __restrict__ Hout)
{
    extern __shared__ __align__(1024) char smem[];
    const int tid = threadIdx.x;

#if HAS_TCGEN05
    const uint32_t sbase = smem_u32(smem);
    // mbars: full[s]=64+16s (cnt 256), empty[s]=+8 (cnt1 commit),
    //        tdone[b]=96+16b (cnt1 commit), dfree[b]=+8 (cnt 128)
    if (tid == 0) {
#pragma unroll
        for (int s = 0; s < 2; s++) {
            mbar_init(sbase + 64 + 16 * s, 256);
            mbar_init(sbase + 64 + 16 * s + 8, 1);
            mbar_init(sbase + 96 + 16 * s, 1);
            mbar_init(sbase + 96 + 16 * s + 8, 128);
        }
    }
    if (tid >= 256 && tid < 288) tc_alloc(sbase, 512);
    __syncthreads();

    uint32_t tmem_base;
    asm volatile("ld.shared.b32 %0, [%1];" : "=r"(tmem_base) : "r"(sbase));

    if (tid < 256) {
        // ------- producers: prefetched LDG -> register split -> STS ----------
        const int r0 = tid >> 3;
        const int c4 = tid & 7;
        uint32_t offA[4], offB[8];
#pragma unroll
        for (int j = 0; j < 4; j++)
            offA[j] = SWZ128((uint32_t)(r0 + 32 * j) * 128 + c4 * 16);
#pragma unroll
        for (int j = 0; j < 8; j++)
            offB[j] = SWZ128((uint32_t)(r0 + 32 * j) * 128 + c4 * 16);

        uint32_t pe[2] = {1, 1};
        float4 rA[4], rB[8];

        // prefetch (tile=blockIdx.x, iter 0)
        int t = blockIdx.x;
        if (t < G1_TILES) {
            const int bm = (t >> 2) * 128;
            const int bn = (t & 3) * 256;
            const float* qA = x  + (size_t)(bm + r0) * D_DIM + c4 * 4;
            const float* qB = W1 + (size_t)(bn + r0) * D_DIM + c4 * 4;
#pragma unroll
            for (int j = 0; j < 4; j++) rA[j] = *(const float4*)(qA + (size_t)(32 * j) * D_DIM);
#pragma unroll
            for (int j = 0; j < 8; j++) rB[j] = *(const float4*)(qB + (size_t)(32 * j) * D_DIM);
        }

        for (; t < G1_TILES; t += gridDim.x) {
            for (int i = 0; i < NIT; i++) {
                const int s = i & 1;
                mbar_wait(sbase + 64 + 16 * s + 8, pe[s]); pe[s] ^= 1;

                char* st = smem + 1024 + s * STAGE_BYTES;
#pragma unroll
                for (int j = 0; j < 4; j++) {
                    float4 h, l; split4(rA[j], h, l);
                    *(float4*)(st + offA[j])           = h;
                    *(float4*)(st + OFF_ALO + offA[j]) = l;
                }
#pragma unroll
                for (int j = 0; j < 8; j++) {
                    float4 h, l; split4(rB[j], h, l);
                    *(float4*)(st + OFF_BHI + offB[j]) = h;
                    *(float4*)(st + OFF_BLO + offB[j]) = l;
                }
                fence_proxy_async_cta();
                mbar_arrive(sbase + 64 + 16 * s);

                // prefetch next (i+1, or next tile's iter 0)
                int ni = i + 1;
                int nt = t;
                if (ni == NIT) { ni = 0; nt = t + gridDim.x; }
                if (nt < G1_TILES) {
                    const int nbm = (nt >> 2) * 128;
                    const int nbn = (nt & 3) * 256;
                    const float* qA = x  + (size_t)(nbm + r0) * D_DIM + c4 * 4 + ni * BK;
                    const float* qB = W1 + (size_t)(nbn + r0) * D_DIM + c4 * 4 + ni * BK;
#pragma unroll
                    for (int j = 0; j < 4; j++) rA[j] = *(const float4*)(qA + (size_t)(32 * j) * D_DIM);
#pragma unroll
                    for (int j = 0; j < 8; j++) rB[j] = *(const float4*)(qB + (size_t)(32 * j) * D_DIM);
                }
            }
        }
    } else if (tid == 256) {
        // ---------------- MMA issuer ----------------------------------------
        uint32_t pf[2] = {0, 0}, pd[2] = {0, 0};
        int lt = 0;
        for (int t = blockIdx.x; t < G1_TILES; t += gridDim.x) {
            const int b = lt & 1;
            if (lt >= 2) { mbar_wait(sbase + 96 + 16 * b + 8, pd[b]); pd[b] ^= 1; }
            const uint32_t dD = tmem_base + b * 256;

            for (int i = 0; i < NIT; i++) {
                const int s = i & 1;
                mbar_wait(sbase + 64 + 16 * s, pf[s]); pf[s] ^= 1;

                uint32_t sb = sbase + 1024 + s * STAGE_BYTES;
                uint64_t dAh = make_desc_sw128(sb);
                uint64_t dAl = make_desc_sw128(sb + OFF_ALO);
                uint64_t dBh = make_desc_sw128(sb + OFF_BHI);
                uint64_t dBl = make_desc_sw128(sb + OFF_BLO);
#pragma unroll
                for (int ks = 0; ks < 4; ks++) {
                    mma_tf32_ss(dD, dAh + 2 * ks, dBh + 2 * ks, IDESC_G1,
                                (i == 0 && ks == 0) ? 0u : 1u);
                    mma_tf32_ss(dD, dAh + 2 * ks, dBl + 2 * ks, IDESC_G1, 1u);
                    mma_tf32_ss(dD, dAl + 2 * ks, dBh + 2 * ks, IDESC_G1, 1u);
                }
                tc_commit(sbase + 64 + 16 * s + 8);
            }
            tc_commit(sbase + 96 + 16 * b);
            lt++;
        }
    } else if (tid >= 288) {
        // ---------------- epilogue: 4 warps, 256 cols each -------------------
        const int sub = (tid >> 5) & 3;
        const int lane = tid & 31;
        uint32_t pt[2] = {0, 0};
        int lt = 0;
        for (int t = blockIdx.x; t < G1_TILES; t += gridDim.x) {
            const int b = lt & 1;
            mbar_wait(sbase + 96 + 16 * b, pt[b]); pt[b] ^= 1;
            tc_fence_after();

            const int bm = (t >> 2) * 128;
            const int bn = (t & 3) * 256;
            const int row = bm + sub * 32 + lane;
            float* hrow = Hout + (size_t)row * H_DIM + bn;
            const float* brow = b1 + bn;
            const uint32_t dD = tmem_base + b * 256;
#pragma unroll
            for (int ch = 0; ch < 8; ch++) {
                uint32_t r[32];
                TC_LD_X32(r, dD + ch * 32);
                tc_wait_ld();
#pragma unroll
                for (int q = 0; q < 8; q++) {
                    float4 bias = *(const float4*)(brow + ch * 32 + q * 4);
                    float4 o;
                    o.x = gelu_erf(__uint_as_float(r[q * 4 + 0]) + bias.x);
                    o.y = gelu_erf(__uint_as_float(r[q * 4 + 1]) + bias.y);
                    o.z = gelu_erf(__uint_as_float(r[q * 4 + 2]) + bias.z);
                    o.w = gelu_erf(__uint_as_float(r[q * 4 + 3]) + bias.w);
                    *(float4*)(hrow + ch * 32 + q * 4) = o;
                }
            }
            tc_fence_before();
            mbar_arrive(sbase + 96 + 16 * b + 8);
            lt++;
        }
    }

    __syncthreads();
    if (tid >= 256 && tid < 288) tc_dealloc(tmem_base, 512);

#else  // ---------- FFMA fallback (generic pass; persistent) -----------------
    float* As = (float*)smem;
    float* Bs = As + 8 * 128;

    const int tx = tid & 15;
    const int ty = tid >> 4;
    const int lr = tid >> 1;
    const int lc = (tid & 1) * 4;

    for (int t = blockIdx.x; t < G1_TILES; t += gridDim.x) {
        const int bm = (t >> 2) * 128;
        for (int half = 0; half < 2; half++) {
            const int bn = (t & 3) * 256 + half * 128;
            float acc[8][8];
#pragma unroll
            for (int i = 0; i < 8; i++)
#pragma unroll
                for (int j = 0; j < 8; j++) acc[i][j] = 0.0f;

            for (int k0 = 0; k0 < D_DIM; k0 += 8) {
                __syncthreads();
                if (tid < 256) {
                    float4 a4 = *(const float4*)(x  + (size_t)(bm + lr) * D_DIM + lc + k0);
                    float4 b4 = *(const float4*)(W1 + (size_t)(bn + lr) * D_DIM + lc + k0);
                    As[(lc + 0) * 128 + lr] = a4.x; As[(lc + 1) * 128 + lr] = a4.y;
                    As[(lc + 2) * 128 + lr] = a4.z; As[(lc + 3) * 128 + lr] = a4.w;
                    Bs[(lc + 0) * 128 + lr] = b4.x; Bs[(lc + 1) * 128 + lr] = b4.y;
                    Bs[(lc + 2) * 128 + lr] = b4.z; Bs[(lc + 3) * 128 + lr] = b4.w;
                }
                __syncthreads();
                if (tid < 256) {
#pragma unroll
                    for (int kk = 0; kk < 8; kk++) {
                        float a[8], b[8];
                        *(float4*)(a)     = *(const float4*)&As[kk * 128 + ty * 8];
                        *(float4*)(a + 4) = *(const float4*)&As[kk * 128 + ty * 8 + 4];
                        *(float4*)(b)     = *(const float4*)&Bs[kk * 128 + tx * 8];
                        *(float4*)(b + 4) = *(const float4*)&Bs[kk * 128 + tx * 8 + 4];
#pragma unroll
                        for (int i = 0; i < 8; i++)
#pragma unroll
                            for (int j = 0; j < 8; j++)
                                acc[i][j] = fmaf(a[i], b[j], acc[i][j]);
                    }
                }
            }

            if (tid < 256) {
                float bias[8];
                *(float4*)(bias)     = *(const float4*)&b1[bn + tx * 8];
                *(float4*)(bias + 4) = *(const float4*)&b1[bn + tx * 8 + 4];
#pragma unroll
                for (int i = 0; i < 8; i++) {
                    const int row = bm + ty * 8 + i;
                    float o[8];
#pragma unroll
                    for (int j = 0; j < 8; j++)
                        o[j] = gelu_erf(acc[i][j] + bias[j]);
                    float* dst = Hout + (size_t)row * H_DIM + bn + tx * 8;
                    *(float4*)(dst)     = make_float4(o[0], o[1], o[2], o[3]);
                    *(float4*)(dst + 4) = make_float4(o[4], o[5], o[6], o[7]);
                }
            }
            __syncthreads();
        }
    }
#endif
}

// ============================================================================
// GEMM2: logits = (H @ W2^T + b2)/temp; top-2 softmax.  3xTF32, 4-stage pipe,
// in-register split, PREFETCHED producers. 288 threads.
// ============================================================================
#define NIT2 (H_DIM / 32)
#define STAGE2_BYTES 49152
#define OFF2_HLO 16384
#define OFF2_WHI 32768
#define OFF2_WLO 40960
#define GEMM2_SMEM (1024 + 4 * STAGE2_BYTES)

#define IDESC_G2 ((1u << 4) | (2u << 7) | (2u << 10) | ((64u / 8) << 17) | ((128u / 16) << 24))

extern "C" __global__ void __launch_bounds__(288, 1) gemm2_kernel(
    const float* __restrict__ Hin, const float* __restrict__ W2,
    const float* __restrict__ b2, const float* __restrict__ log_temp,
    float* __restrict__ out)
{
    extern __shared__ __align__(1024) char smem[];
    const int tid = threadIdx.x;
    const int bm = blockIdx.x * 128;

#if HAS_TCGEN05
    const uint32_t sbase = smem_u32(smem);

    if (tid == 0) {
#pragma unroll
        for (int s = 0; s < 4; s++) {
            mbar_init(sbase + 64 + 16 * s, 256);
            mbar_init(sbase + 64 + 16 * s + 8, 1);
        }
    }
    if (tid >= 256) tc_alloc(sbase, 64);
    __syncthreads();

    uint32_t tmem_base;
    asm volatile("ld.shared.b32 %0, [%1];" : "=r"(tmem_base) : "r"(sbase));

    if (tid < 256) {
        const int r0 = tid >> 3;
        const int c4 = tid & 7;
        uint32_t offH[4], offW[2];
#pragma unroll
        for (int j = 0; j < 4; j++)
            offH[j] = SWZ128((uint32_t)(r0 + 32 * j) * 128 + c4 * 16);
#pragma unroll
        for (int j = 0; j < 2; j++)
            offW[j] = SWZ128((uint32_t)(r0 + 32 * j) * 128 + c4 * 16);

        const float* pH = Hin + (size_t)(bm + r0) * H_DIM + c4 * 4;
        const float* pW = W2  + (size_t)r0 * H_DIM + c4 * 4;

        uint32_t pe[4] = {1, 1, 1, 1};
        float4 rH[4], rW[2];

        // prefetch iter 0
#pragma unroll
        for (int j = 0; j < 4; j++) rH[j] = *(const float4*)(pH + (size_t)(32 * j) * H_DIM);
#pragma unroll
        for (int j = 0; j < 2; j++) rW[j] = *(const float4*)(pW + (size_t)(32 * j) * H_DIM);

        for (int i = 0; i < NIT2; i++) {
            const int s = i & 3;
            const uint32_t mb_full  = sbase + 64 + 16 * s;
            const uint32_t mb_empty = mb_full + 8;
            mbar_wait(mb_empty, pe[s]); pe[s] ^= 1;

            char* st = smem + 1024 + s * STAGE2_BYTES;
#pragma unroll
            for (int j = 0; j < 4; j++) {
                float4 h, l; split4(rH[j], h, l);
                *(float4*)(st + offH[j])            = h;
                *(float4*)(st + OFF2_HLO + offH[j]) = l;
            }
#pragma unroll
            for (int j = 0; j < 2; j++) {
                float4 h, l; split4(rW[j], h, l);
                *(float4*)(st + OFF2_WHI + offW[j]) = h;
                *(float4*)(st + OFF2_WLO + offW[j]) = l;
            }
            fence_proxy_async_cta();
            mbar_arrive(mb_full);

            if (i + 1 < NIT2) {
                const int k0 = (i + 1) * 32;
#pragma unroll
                for (int j = 0; j < 4; j++) rH[j] = *(const float4*)(pH + (size_t)(32 * j) * H_DIM + k0);
#pragma unroll
                for (int j = 0; j < 2; j++) rW[j] = *(const float4*)(pW + (size_t)(32 * j) * H_DIM + k0);
            }
        }

#pragma unroll
        for (int s = 0; s < 4; s++)
            mbar_wait(sbase + 64 + 16 * s + 8, pe[s]);
        tc_fence_after();
    } else if (tid == 256) {
        uint32_t pf[4] = {0, 0, 0, 0};
        for (int i = 0; i < NIT2; i++) {
            const int s = i & 3;
            const uint32_t mb_full  = sbase + 64 + 16 * s;
            const uint32_t mb_empty = mb_full + 8;
            mbar_wait(mb_full, pf[s]); pf[s] ^= 1;

            uint32_t sb = sbase + 1024 + s * STAGE2_BYTES;
            uint64_t dHh = make_desc_sw128(sb);
            uint64_t dHl = make_desc_sw128(sb + OFF2_HLO);
            uint64_t dWh = make_desc_sw128(sb + OFF2_WHI);
            uint64_t dWl = make_desc_sw128(sb + OFF2_WLO);
#pragma unroll
            for (int ks = 0; ks < 4; ks++) {
                mma_tf32_ss(tmem_base, dHh + 2 * ks, dWh + 2 * ks, IDESC_G2,
                            (i == 0 && ks == 0) ? 0u : 1u);
                mma_tf32_ss(tmem_base, dHh + 2 * ks, dWl + 2 * ks, IDESC_G2, 1u);
                mma_tf32_ss(tmem_base, dHl + 2 * ks, dWh + 2 * ks, IDESC_G2, 1u);
            }
            tc_commit(mb_empty);
        }
    }
    __syncthreads();

    float* Ls  = (float*)(smem + 1024);            // [128][65]
    float* p1s = (float*)(smem + 1024 + 33280);
    float* p2s = p1s + 128;
    int*   i1s = (int*)(p2s + 128);
    int*   i2s = i1s + 128;

    float t = expf(*log_temp);
    t = fminf(fmaxf(t, 1e-3f), 100.0f);
    const float it = 1.0f / t;

    if (tid < 256) {
        const int w = tid >> 5, lane = tid & 31;
        const int row = (w & 3) * 32 + lane;
        const int colbase = (w >> 2) * 32;
        uint32_t r[32];
        TC_LD_X32(r, tmem_base + colbase);
        tc_wait_ld();
#pragma unroll
        for (int c = 0; c < 32; c++)
            Ls[row * 65 + colbase + c] =
                (__uint_as_float(r[c]) + b2[colbase + c]) * it;
    }
    __syncthreads();

    if (tid < 128) {
        float m1 = -INFINITY, m2 = -INFINITY;
        int i1 = -1, i2 = -1;
#pragma unroll 8
        for (int e = 0; e < E_DIM; e++) {
            float v = Ls[tid * 65 + e];
            if (v > m1) { m2 = m1; i2 = i1; m1 = v; i1 = e; }
            else if (v > m2) { m2 = v; i2 = e; }
        }
        float ed = expf(m2 - m1);
        float s = 1.0f / (1.0f + ed);
        p1s[tid] = s;
        p2s[tid] = ed * s;
        i1s[tid] = i1;
        i2s[tid] = i2;
    }
    __syncthreads();

    if (tid < 256) {
        for (int idx = tid; idx < 128 * E_DIM; idx += 256) {
            const int r = idx >> 6;
            const int e = idx & 63;
            float v = 0.0f;
            if (e == i1s[r]) v = p1s[r];
            else if (e == i2s[r]) v = p2s[r];
            out[(size_t)(bm + r) * E_DIM + e] = v;
        }
    }

    __syncthreads();
    if (tid >= 256) tc_dealloc(tmem_base, 64);

#else  // ---------- FFMA fallback (generic pass) -----------------------------
    float* Hs  = (float*)smem;
    float* Ws  = Hs + 16 * 128;
    float* Ls  = Ws + 16 * 64;
    float* p1s = Ls + 128 * 65;
    float* p2s = p1s + 128;
    int*   i1s = (int*)(p2s + 128);
    int*   i2s = i1s + 128;

    const int tx = tid & 15;
    const int ty = tid >> 4;
    const int hr0 = tid >> 2;
    const int hc0 = (tid & 3) * 4;
    const int hr1 = (tid + 256) >> 2;
    const int wr = tid >> 2;
    const int wc = (tid & 3) * 4;

    float acc[8][4];
#pragma unroll
    for (int i = 0; i < 8; i++)
#pragma unroll
        for (int j = 0; j < 4; j++) acc[i][j] = 0.0f;

    for (int k0 = 0; k0 < H_DIM; k0 += 16) {
        __syncthreads();
        if (tid < 256) {
            float4 h0 = *(const float4*)(Hin + (size_t)(bm + hr0) * H_DIM + k0 + hc0);
            float4 h1 = *(const float4*)(Hin + (size_t)(bm + hr1) * H_DIM + k0 + hc0);
            float4 w4 = *(const float4*)(W2  + (size_t)wr * H_DIM + k0 + wc);
            Hs[(hc0 + 0) * 128 + hr0] = h0.x; Hs[(hc0 + 1) * 128 + hr0] = h0.y;
            Hs[(hc0 + 2) * 128 + hr0] = h0.z; Hs[(hc0 + 3) * 128 + hr0] = h0.w;
            Hs[(hc0 + 0) * 128 + hr1] = h1.x; Hs[(hc0 + 1) * 128 + hr1] = h1.y;
            Hs[(hc0 + 2) * 128 + hr1] = h1.z; Hs[(hc0 + 3) * 128 + hr1] = h1.w;
            Ws[(wc + 0) * 64 + wr] = w4.x; Ws[(wc + 1) * 64 + wr] = w4.y;
            Ws[(wc + 2) * 64 + wr] = w4.z; Ws[(wc + 3) * 64 + wr] = w4.w;
        }
        __syncthreads();
        if (tid < 256) {
#pragma unroll
            for (int kk = 0; kk < 16; kk++) {
                float a[8], b[4];
                *(float4*)(a)     = *(const float4*)&Hs[kk * 128 + ty * 8];
                *(float4*)(a + 4) = *(const float4*)&Hs[kk * 128 + ty * 8 + 4];
                *(float4*)(b)     = *(const float4*)&Ws[kk * 64 + tx * 4];
#pragma unroll
                for (int i = 0; i < 8; i++)
#pragma unroll
                    for (int j = 0; j < 4; j++)
                        acc[i][j] = fmaf(a[i], b[j], acc[i][j]);
            }
        }
    }

    float t = expf(*log_temp);
    t = fminf(fmaxf(t, 1e-3f), 100.0f);
    const float it = 1.0f / t;

    if (tid < 256) {
#pragma unroll
        for (int i = 0; i < 8; i++)
#pragma unroll
            for (int j = 0; j < 4; j++) {
                const int col = tx * 4 + j;
                Ls[(ty * 8 + i) * 65 + col] = (acc[i][j] + b2[col]) * it;
            }
    }
    __syncthreads();

    if (tid < 128) {
        float m1 = -INFINITY, m2 = -INFINITY;
        int i1 = -1, i2 = -1;
#pragma unroll 8
        for (int e = 0; e < E_DIM; e++) {
            float v = Ls[tid * 65 + e];
            if (v > m1) { m2 = m1; i2 = i1; m1 = v; i1 = e; }
            else if (v > m2) { m2 = v; i2 = e; }
        }
        float ed = expf(m2 - m1);
        float s = 1.0f / (1.0f + ed);
        p1s[tid] = s;
        p2s[tid] = ed * s;
        i1s[tid] = i1;
        i2s[tid] = i2;
    }
    __syncthreads();

    if (tid < 256) {
        for (int idx = tid; idx < 128 * E_DIM; idx += 256) {
            const int r = idx >> 6;
            const int e = idx & 63;
            float v = 0.0f;
            if (e == i1s[r]) v = p1s[r];
            else if (e == i2s[r]) v = p2s[r];
            out[(size_t)(bm + r) * E_DIM + e] = v;
        }
    }
#endif
}

// ---------------- launcher ---------------------------------------------------
extern "C" void kernel_launch(void* const* d_in, const int* in_sizes, int n_in,
                              void* d_out, int out_size) {
    const float* x  = (const float*)d_in[0];
    const float* W1 = (const float*)d_in[1];
    const float* b1 = (const float*)d_in[2];
    const float* W2 = (const float*)d_in[3];
    const float* b2 = (const float*)d_in[4];
    const float* lt = (const float*)d_in[5];
    float* out = (float*)d_out;

    const int M = in_sizes[0] / D_DIM;   // 65536

    float* Hbuf;
    cudaGetSymbolAddress((void**)&Hbuf, g_H);

    static int nsm = 0;
    if (!nsm) {
        cudaDeviceGetAttribute(&nsm, cudaDevAttrMultiProcessorCount, 0);
        cudaFuncSetAttribute(gemm1_kernel,
                             cudaFuncAttributeMaxDynamicSharedMemorySize, GEMM1_SMEM);
        cudaFuncSetAttribute(gemm2_kernel,
                             cudaFuncAttributeMaxDynamicSharedMemorySize, GEMM2_SMEM);
    }

    gemm1_kernel<<<nsm, 416, GEMM1_SMEM>>>(x, W1, b1, Hbuf);

    dim3 grid2(M / 128);
    gemm2_kernel<<<grid2, 288, GEMM2_SMEM>>>(Hbuf, W2, b2, lt, out);
}